// round 12
// baseline (speedup 1.0000x reference)
#include <cuda_runtime.h>
#include <cuda_bf16.h>
#include <cuda_fp16.h>
#include <cstdint>

#define NMAX 100000
#define EMAX 1600000
#define BCAP 64                 // fixed bucket capacity per node
#define OVFCAP 32768            // overflow edges (deg > BCAP), ~never used

typedef unsigned long long ull;

// ---------------- device scratch (static: no runtime allocation) ------------
__device__ __half2 g_hh[(size_t)NMAX * 64];   // x @ W   [N,128] as half2[N,64]
__device__ float   g_asrc[NMAX * 4];          // per-node att logits (src side)
__device__ float   g_adst[NMAX * 4];          // per-node att logits (dst side)
__device__ int     g_cursor[NMAX];            // per-node degree counter
__device__ int     g_bucket[(size_t)NMAX * BCAP];  // src ids, fixed slots per dst
__device__ int2    g_ovf[OVFCAP];             // (dst, src) overflow edges
__device__ int     g_ovfcnt;
__device__ float   g_colsum[128];
__device__ float   g_colsq[128];
__device__ float   g_scale[128];
__device__ float   g_shift[128];
__device__ int     g_is64;                    // edge_index dtype flag

// ---------------- init (+ fused edge dtype detection) -----------------------
__global__ void init_kernel(const int* __restrict__ w, int n) {
    int i = blockIdx.x * blockDim.x + threadIdx.x;
    if (i == 0) {
        int all0 = 1;
        for (int j = 1; j < 64; j += 2) all0 &= (w[j] == 0);
        g_is64 = all0;
        g_ovfcnt = 0;
    }
    if (i < n) g_cursor[i] = 0;
    if (i < 128) { g_colsum[i] = 0.f; g_colsq[i] = 0.f; }
}

// ---------------- GEMM via mma.sync bf16 2-term split, fused logits ---------
#define MMA_BF16(d, a0, a1, a2, a3, b0, b1) \
    asm volatile("mma.sync.aligned.m16n8k16.row.col.f32.bf16.bf16.f32 " \
        "{%0,%1,%2,%3}, {%4,%5,%6,%7}, {%8,%9}, {%0,%1,%2,%3};" \
        : "+f"((d)[0]), "+f"((d)[1]), "+f"((d)[2]), "+f"((d)[3]) \
        : "r"(a0), "r"(a1), "r"(a2), "r"(a3), "r"(b0), "r"(b1))

static constexpr int AST = 136;                       // bf16 row stride (conflict-free)
static constexpr int SZ_TILE = 128 * AST * 2;         // 34816 B per bf16 tile
static constexpr int SM_AHI = 0;
static constexpr int SM_ALO = SM_AHI + SZ_TILE;
static constexpr int SM_BHI = SM_ALO + SZ_TILE;       // Wt [n][k]
static constexpr int SM_BLO = SM_BHI + SZ_TILE;
static constexpr int SM_ATT = SM_BLO + SZ_TILE;       // 256 floats (src|dst)
static constexpr int GEMM_SMEM = SM_ATT + 1024;       // 140288 B

__global__ __launch_bounds__(256, 1) void gemm_mma_kernel(
    const float4* __restrict__ x4, const float* __restrict__ W,
    const float* __restrict__ att_src, const float* __restrict__ att_dst,
    int n)
{
    extern __shared__ char smem[];
    __nv_bfloat16* sAhi = (__nv_bfloat16*)(smem + SM_AHI);
    __nv_bfloat16* sAlo = (__nv_bfloat16*)(smem + SM_ALO);
    __nv_bfloat16* sBhi = (__nv_bfloat16*)(smem + SM_BHI);
    __nv_bfloat16* sBlo = (__nv_bfloat16*)(smem + SM_BLO);
    float* s_att = (float*)(smem + SM_ATT);           // [0:128) src, [128:256) dst

    const int tid = threadIdx.x;
    const int row0 = blockIdx.x * 128;

    if (tid < 128) { s_att[tid] = att_src[tid]; s_att[128 + tid] = att_dst[tid]; }

    for (int i = tid; i < 128 * 128; i += 256) {
        int k = i >> 7, nn = i & 127;
        float w = W[i];
        __nv_bfloat16 hi = __float2bfloat16(w);
        __nv_bfloat16 lo = __float2bfloat16(w - __bfloat162float(hi));
        sBhi[nn * AST + k] = hi;
        sBlo[nn * AST + k] = lo;
    }
    for (int i = tid; i < 128 * 32; i += 256) {
        int r = i >> 5, q = i & 31;
        int grow = row0 + r;
        float4 v = make_float4(0.f, 0.f, 0.f, 0.f);
        if (grow < n) v = x4[(size_t)grow * 32 + q];
        __nv_bfloat162 h0 = __floats2bfloat162_rn(v.x, v.y);
        __nv_bfloat162 h1 = __floats2bfloat162_rn(v.z, v.w);
        __nv_bfloat162 l0 = __floats2bfloat162_rn(v.x - __bfloat162float(h0.x),
                                                  v.y - __bfloat162float(h0.y));
        __nv_bfloat162 l1 = __floats2bfloat162_rn(v.z - __bfloat162float(h1.x),
                                                  v.w - __bfloat162float(h1.y));
        uint32_t base = r * AST + q * 4;
        *(uint32_t*)&sAhi[base]     = *(uint32_t*)&h0;
        *(uint32_t*)&sAhi[base + 2] = *(uint32_t*)&h1;
        *(uint32_t*)&sAlo[base]     = *(uint32_t*)&l0;
        *(uint32_t*)&sAlo[base + 2] = *(uint32_t*)&l1;
    }
    __syncthreads();

    const int lane = tid & 31, warp = tid >> 5;
    const int g = lane >> 2, tig = lane & 3;
    const int mrow = warp * 16;

    float d[16][4];
#pragma unroll
    for (int nt = 0; nt < 16; nt++)
#pragma unroll
        for (int j = 0; j < 4; j++) d[nt][j] = 0.f;

#pragma unroll
    for (int term = 0; term < 3; term++) {
        const __nv_bfloat16* A = (term == 2) ? sAlo : sAhi;
        const __nv_bfloat16* B = (term == 1) ? sBlo : sBhi;
#pragma unroll
        for (int k0 = 0; k0 < 128; k0 += 16) {
            int kc = k0 + tig * 2;
            uint32_t a0 = *(const uint32_t*)&A[(mrow + g) * AST + kc];
            uint32_t a1 = *(const uint32_t*)&A[(mrow + g + 8) * AST + kc];
            uint32_t a2 = *(const uint32_t*)&A[(mrow + g) * AST + kc + 8];
            uint32_t a3 = *(const uint32_t*)&A[(mrow + g + 8) * AST + kc + 8];
#pragma unroll
            for (int nt = 0; nt < 16; nt++) {
                uint32_t b0 = *(const uint32_t*)&B[(nt * 8 + g) * AST + kc];
                uint32_t b1 = *(const uint32_t*)&B[(nt * 8 + g) * AST + kc + 8];
                MMA_BF16(d[nt], a0, a1, a2, a3, b0, b1);
            }
        }
    }

    const int r0 = row0 + mrow + g;
    const int r1 = r0 + 8;
    float ps0[4], pd0[4], ps1[4], pd1[4];
#pragma unroll
    for (int h = 0; h < 4; h++) { ps0[h] = pd0[h] = ps1[h] = pd1[h] = 0.f; }
#pragma unroll
    for (int nt = 0; nt < 16; nt++) {
        int c0 = nt * 8 + tig * 2;
        int h = nt >> 2;
        float a_s0 = s_att[c0], a_s1 = s_att[c0 + 1];
        float a_d0 = s_att[128 + c0], a_d1 = s_att[128 + c0 + 1];
        ps0[h] += d[nt][0] * a_s0 + d[nt][1] * a_s1;
        pd0[h] += d[nt][0] * a_d0 + d[nt][1] * a_d1;
        ps1[h] += d[nt][2] * a_s0 + d[nt][3] * a_s1;
        pd1[h] += d[nt][2] * a_d0 + d[nt][3] * a_d1;
        if (r0 < n) g_hh[(size_t)r0 * 64 + (c0 >> 1)] = __floats2half2_rn(d[nt][0], d[nt][1]);
        if (r1 < n) g_hh[(size_t)r1 * 64 + (c0 >> 1)] = __floats2half2_rn(d[nt][2], d[nt][3]);
    }
#pragma unroll
    for (int h = 0; h < 4; h++) {
#pragma unroll
        for (int off = 1; off <= 2; off <<= 1) {
            ps0[h] += __shfl_xor_sync(0xffffffffu, ps0[h], off);
            pd0[h] += __shfl_xor_sync(0xffffffffu, pd0[h], off);
            ps1[h] += __shfl_xor_sync(0xffffffffu, ps1[h], off);
            pd1[h] += __shfl_xor_sync(0xffffffffu, pd1[h], off);
        }
    }
    if (tig == 0) {
#pragma unroll
        for (int h = 0; h < 4; h++) {
            if (r0 < n) { g_asrc[r0 * 4 + h] = ps0[h]; g_adst[r0 * 4 + h] = pd0[h]; }
            if (r1 < n) { g_asrc[r1 * 4 + h] = ps1[h]; g_adst[r1 * 4 + h] = pd1[h]; }
        }
    }
}

// ---------------- single-pass bucket scatter ---------------------------------
__global__ void scatter_kernel(const int* __restrict__ w, int e, int n) {
    int i = blockIdx.x * blockDim.x + threadIdx.x;
    if (i < e) {
        int is64 = g_is64;
        int s = is64 ? w[2 * (size_t)i]       : w[i];
        int d = is64 ? w[2 * (size_t)(e + i)] : w[(size_t)e + i];
        if ((unsigned)s < (unsigned)n && (unsigned)d < (unsigned)n) {
            int pos = atomicAdd(&g_cursor[d], 1);
            if (pos < BCAP) {
                g_bucket[(size_t)d * BCAP + pos] = s;
            } else {
                int oi = atomicAdd(&g_ovfcnt, 1);
                if (oi < OVFCAP) g_ovf[oi] = make_int2(d, s);
            }
        }
    }
}

// ---------------- warp-per-node softmax aggregation ------------------------
// 8 edges/iter: lane l owns exp for edge (l&7) on head (l>>3); consumers take
// p and the 32-bit row offset via shuffle. One asrc LDG + one exp per 8 edges.
__global__ __launch_bounds__(256) void aggregate_kernel(
    const float4* __restrict__ gat_bias4, float4* __restrict__ out4, int n)
{
    __shared__ float rsum[8][132];
    __shared__ float rsq[8][132];
    const int t = threadIdx.x;
    const int lane = t & 31;
    const int wid = t >> 5;
    const int node = blockIdx.x * 8 + wid;

    float4 o = make_float4(0.f, 0.f, 0.f, 0.f);
    float4 osq = make_float4(0.f, 0.f, 0.f, 0.f);

    if (node < n) {
        const int head = lane >> 3;
        const int myj = lane & 7;
        const int hsel = lane & 24;            // (head*8)
        const float ad = g_adst[node * 4 + head];
        float e0 = g_asrc[node * 4 + head] + ad;
        e0 = e0 > 0.f ? e0 : 0.2f * e0;
        float p0 = __expf(e0);
        float sa = p0;
        const __half2* hh = g_hh;
        __half2 v0 = hh[(size_t)node * 64 + lane * 2];
        __half2 v1 = hh[(size_t)node * 64 + lane * 2 + 1];
        float2 f0 = __half22float2(v0), f1 = __half22float2(v1);
        float4 acc = make_float4(p0 * f0.x, p0 * f0.y, p0 * f1.x, p0 * f1.y);

        const int deg = g_cursor[node];
        const int cnt = deg < BCAP ? deg : BCAP;
        const int* bp = &g_bucket[(size_t)node * BCAP];
        int i = 0;
        for (; i + 8 <= cnt; i += 8) {
            // lane-parallel logits: one edge-head pair per lane
            int src_l = bp[i + myj];
            float el = g_asrc[src_l * 4 + head] + ad;
            el = el > 0.f ? el : 0.2f * el;
            float pl = __expf(el);
            int off_l = src_l * 64;            // half2-row offset (32-bit)
#pragma unroll
            for (int j = 0; j < 8; j++) {
                float pj = __shfl_sync(0xffffffffu, pl, hsel + j);
                int offj = __shfl_sync(0xffffffffu, off_l, hsel + j);
                uint2 u = *(const uint2*)&hh[(size_t)(unsigned)offj + lane * 2];
                float2 a0 = __half22float2(*(__half2*)&u.x);
                float2 a1 = __half22float2(*(__half2*)&u.y);
                sa += pj;
                acc.x = fmaf(pj, a0.x, acc.x);
                acc.y = fmaf(pj, a0.y, acc.y);
                acc.z = fmaf(pj, a1.x, acc.z);
                acc.w = fmaf(pj, a1.y, acc.w);
            }
        }
        for (; i < cnt; i++) {
            int s0 = bp[i];
            float ea = g_asrc[s0 * 4 + head] + ad;
            uint2 ua = *(const uint2*)&hh[(size_t)s0 * 64 + lane * 2];
            ea = ea > 0.f ? ea : 0.2f * ea;
            float pa = __expf(ea);
            sa += pa;
            float2 a0 = __half22float2(*(__half2*)&ua.x), a1 = __half22float2(*(__half2*)&ua.y);
            acc.x = fmaf(pa, a0.x, acc.x);
            acc.y = fmaf(pa, a0.y, acc.y);
            acc.z = fmaf(pa, a1.x, acc.z);
            acc.w = fmaf(pa, a1.y, acc.w);
        }
        // overflow edges (deg > BCAP): ~never taken, one load when empty
        if (deg > BCAP) {
            int oc = g_ovfcnt;
            oc = oc < OVFCAP ? oc : OVFCAP;
            for (int k = 0; k < oc; k++) {
                int2 p = g_ovf[k];
                if (p.x == node) {
                    int s0 = p.y;
                    float ea = g_asrc[s0 * 4 + head] + ad;
                    uint2 ua = *(const uint2*)&hh[(size_t)s0 * 64 + lane * 2];
                    ea = ea > 0.f ? ea : 0.2f * ea;
                    float pa = __expf(ea);
                    sa += pa;
                    float2 a0 = __half22float2(*(__half2*)&ua.x);
                    float2 a1 = __half22float2(*(__half2*)&ua.y);
                    acc.x = fmaf(pa, a0.x, acc.x);
                    acc.y = fmaf(pa, a0.y, acc.y);
                    acc.z = fmaf(pa, a1.x, acc.z);
                    acc.w = fmaf(pa, a1.y, acc.w);
                }
            }
        }
        float inv = 1.0f / sa;
        float4 b = gat_bias4[lane];
        o.x = acc.x * inv + b.x;
        o.y = acc.y * inv + b.y;
        o.z = acc.z * inv + b.z;
        o.w = acc.w * inv + b.w;
        out4[(size_t)node * 32 + lane] = o;
        osq = make_float4(o.x * o.x, o.y * o.y, o.z * o.z, o.w * o.w);
    }

    // conflict-free staged BN reduction
    *(float4*)&rsum[wid][lane * 4] = o;
    *(float4*)&rsq[wid][lane * 4]  = osq;
    __syncthreads();
    if (t < 128) {
        float s = 0.f, q = 0.f;
#pragma unroll
        for (int w = 0; w < 8; w++) { s += rsum[w][t]; q += rsq[w][t]; }
        atomicAdd(&g_colsum[t], s);
        atomicAdd(&g_colsq[t], q);
    }
}

// ---------------- BN stats + final elementwise ------------------------------
__global__ void stats_kernel(const float* __restrict__ gamma,
                             const float* __restrict__ beta, int n) {
    int t = threadIdx.x;
    float invn = 1.0f / (float)n;
    float mean = g_colsum[t] * invn;
    float var = g_colsq[t] * invn - mean * mean;
    float sc = gamma[t] * rsqrtf(var + 1e-5f);
    g_scale[t] = sc;
    g_shift[t] = beta[t] - mean * sc;
}

__global__ void final_kernel(const float4* __restrict__ x4,
                             float4* __restrict__ out4, int n)
{
    int i = blockIdx.x * blockDim.x + threadIdx.x;
    int total4 = n * 32;
    if (i < total4) {
        int c = (i & 31) * 4;
        float4 sc = *(const float4*)&g_scale[c];
        float4 sh = *(const float4*)&g_shift[c];
        float4 o = out4[i];
        float4 xv = x4[i];
        o.x = fmaxf(fmaf(sc.x, o.x, sh.x) + xv.x, 0.f);
        o.y = fmaxf(fmaf(sc.y, o.y, sh.y) + xv.y, 0.f);
        o.z = fmaxf(fmaf(sc.z, o.z, sh.z) + xv.z, 0.f);
        o.w = fmaxf(fmaf(sc.w, o.w, sh.w) + xv.w, 0.f);
        out4[i] = o;
    }
}

// ---------------- launch ----------------------------------------------------
extern "C" void kernel_launch(void* const* d_in, const int* in_sizes, int n_in,
                              void* d_out, int out_size)
{
    const float4* x4        = (const float4*)d_in[0];
    const int*    ew        = (const int*)d_in[1];    // edge words (int32 view)
    const float*  W         = (const float*)d_in[2];
    const float*  att_src   = (const float*)d_in[3];
    const float*  att_dst   = (const float*)d_in[4];
    const float4* gat_bias4 = (const float4*)d_in[5];
    const float*  bn_gamma  = (const float*)d_in[6];
    const float*  bn_beta   = (const float*)d_in[7];
    float4* out4 = (float4*)d_out;

    const int n = in_sizes[0] / 128;
    const int e = in_sizes[1] / 2;

    static cudaStream_t s1 = nullptr;
    static cudaEvent_t evFork = nullptr, evJoin = nullptr;
    if (s1 == nullptr) {
        cudaStreamCreateWithFlags(&s1, cudaStreamNonBlocking);
        cudaEventCreateWithFlags(&evFork, cudaEventDisableTiming);
        cudaEventCreateWithFlags(&evJoin, cudaEventDisableTiming);
        cudaFuncSetAttribute(gemm_mma_kernel,
                             cudaFuncAttributeMaxDynamicSharedMemorySize, GEMM_SMEM);
    }

    init_kernel<<<(n + 255) / 256, 256>>>(ew, n);
    cudaEventRecord(evFork, 0);
    cudaStreamWaitEvent(s1, evFork, 0);

    // branch B: single-pass bucket scatter on s1
    scatter_kernel<<<(e + 255) / 256, 256, 0, s1>>>(ew, e, n);
    cudaEventRecord(evJoin, s1);

    // branch A: tensor-core GEMM on default stream (concurrent with branch B)
    gemm_mma_kernel<<<(n + 127) / 128, 256, GEMM_SMEM>>>(x4, W, att_src, att_dst, n);

    // join
    cudaStreamWaitEvent(0, evJoin, 0);
    aggregate_kernel<<<(n + 7) / 8, 256>>>(gat_bias4, out4, n);
    stats_kernel<<<1, 128>>>(bn_gamma, bn_beta, n);
    final_kernel<<<(n * 32 + 255) / 256, 256>>>(x4, out4, n);
}